// round 6
// baseline (speedup 1.0000x reference)
#include <cuda_runtime.h>
#include <cuda_fp16.h>
#include <cstdint>

#define NPTS  100000
#define KVOL  27
#define PAIRS 60000
#define NPTOT (KVOL * PAIRS)          // 1,620,000 pairs
#define CCH   64
#define TP    128
#define NTILES ((PAIRS + TP - 1) / TP)
#define NSCAN  100352                 // 196 * 512 >= NPTS+1

// smem for pass A: A 128x64 tf32 (swizzled 256B rows) | B 64x64 tf32 | maps
#define SA_OFF 0
#define SB_OFF 32768
#define MAPS_OFF 49152
#define SMEM_BYTES 50176

// ---- global scratch (statically declared; no allocation) ----
__device__ int g_cnt[NSCAN];
__device__ int g_start[NSCAN];
__device__ int g_cursor[NPTS];
__device__ int g_bsum[196];
__device__ int g_bpref[196];
__device__ int g_perm[NPTOT];
__device__ unsigned int g_stage[NPTOT * 32];   // fp16 staging: 64 halves/row, 207MB

__device__ __forceinline__ uint32_t smem_u32(const void* p) {
    uint32_t a;
    asm("{ .reg .u64 t; cvta.to.shared.u64 t, %1; cvt.u32.u64 %0, t; }"
        : "=r"(a) : "l"(p));
    return a;
}

__device__ __forceinline__ uint32_t f2tf32(float f) {
    uint32_t r;
    asm("cvt.rna.tf32.f32 %0, %1;" : "=r"(r) : "f"(f));
    return r;
}

#define LDSM_X4(r0, r1, r2, r3, addr) \
    asm volatile("ldmatrix.sync.aligned.m8n8.x4.shared.b16 {%0,%1,%2,%3}, [%4];" \
                 : "=r"(r0), "=r"(r1), "=r"(r2), "=r"(r3) : "r"(addr))

#define MMA_TF32(c, a0, a1, a2, a3, b0, b1) \
    asm volatile("mma.sync.aligned.m16n8k8.row.col.f32.tf32.tf32.f32 " \
                 "{%0,%1,%2,%3}, {%4,%5,%6,%7}, {%8,%9}, {%0,%1,%2,%3};" \
                 : "+f"(c[0]), "+f"(c[1]), "+f"(c[2]), "+f"(c[3]) \
                 : "r"(a0), "r"(a1), "r"(a2), "r"(a3), "r"(b0), "r"(b1))

// ---------------- prepass kernels ----------------

__global__ void __launch_bounds__(256) zero_cnt_kernel() {
    int i = blockIdx.x * 256 + threadIdx.x;
    if (i < NSCAN) g_cnt[i] = 0;
}

__global__ void __launch_bounds__(256) hist_kernel(const int* __restrict__ out_map) {
    int j = blockIdx.x * 256 + threadIdx.x;
    if (j < NPTOT) atomicAdd(&g_cnt[out_map[j]], 1);
}

__global__ void __launch_bounds__(512) scan_a_kernel() {
    __shared__ int s[512];
    int t = threadIdx.x;
    int i = blockIdx.x * 512 + t;
    int v = (i < NSCAN) ? g_cnt[i] : 0;
    s[t] = v;
    __syncthreads();
    #pragma unroll
    for (int off = 1; off < 512; off <<= 1) {
        int x = (t >= off) ? s[t - off] : 0;
        __syncthreads();
        s[t] += x;
        __syncthreads();
    }
    if (i < NSCAN) g_start[i] = s[t] - v;       // exclusive within block
    if (t == 511) g_bsum[blockIdx.x] = s[511];
}

__global__ void __launch_bounds__(256) scan_b_kernel() {
    __shared__ int s[256];
    int t = threadIdx.x;
    int v = (t < 196) ? g_bsum[t] : 0;
    s[t] = v;
    __syncthreads();
    #pragma unroll
    for (int off = 1; off < 256; off <<= 1) {
        int x = (t >= off) ? s[t - off] : 0;
        __syncthreads();
        s[t] += x;
        __syncthreads();
    }
    if (t < 196) g_bpref[t] = s[t] - v;         // exclusive block prefix
}

__global__ void __launch_bounds__(512) scan_c_kernel() {
    int t = threadIdx.x;
    int i = blockIdx.x * 512 + t;
    if (i < NSCAN) {
        int st = g_start[i] + g_bpref[blockIdx.x];
        g_start[i] = st;
        if (i < NPTS) g_cursor[i] = st;
    }
}

__global__ void __launch_bounds__(256) scatter_perm_kernel(const int* __restrict__ out_map) {
    int j = blockIdx.x * 256 + threadIdx.x;
    if (j < NPTOT) {
        int o = out_map[j];
        g_perm[j] = atomicAdd(&g_cursor[o], 1);
    }
}

// ---------------- pass A: gather + tf32 mma GEMM + sorted fp16 store ----------------

// swizzled byte offset inside a 256B row: chunk' = k16 ^ (row & 7)
__device__ __forceinline__ uint32_t sw_off(int row, int k16) {
    return (uint32_t)(row * 256 + ((k16 ^ (row & 7)) << 4));
}

__global__ void __launch_bounds__(128, 4) pass_a_kernel(
    const float* __restrict__ input,
    const float* __restrict__ kernel,
    const int*   __restrict__ in_map)
{
    extern __shared__ __align__(1024) char smem[];
    const uint32_t sb = smem_u32(smem);
    int* sIn   = (int*)(smem + MAPS_OFF);
    int* sPerm = sIn + TP;

    const int k    = blockIdx.y;
    const int base = blockIdx.x * TP;
    const int tid  = threadIdx.x;
    const int w    = tid >> 5;
    const int l    = tid & 31;
    const int nrem = min(TP, PAIRS - base);

    if (tid < nrem) {
        sIn[tid]   = in_map[k * PAIRS + base + tid];
        sPerm[tid] = g_perm[k * PAIRS + base + tid];
    } else {
        sIn[tid] = -1;
        sPerm[tid] = -1;
    }
    __syncthreads();

    // gather X -> sA (tf32, swizzled); 16 lanes per row -> coalesced
    #pragma unroll
    for (int s = 0; s < 16; s++) {
        int m   = tid + 128 * s;
        int p   = m >> 4;
        int j16 = m & 15;
        int row = sIn[p];
        float4 v = make_float4(0.f, 0.f, 0.f, 0.f);
        if (row >= 0) v = ((const float4*)input)[row * (CCH / 4) + j16];
        uint4 t;
        t.x = f2tf32(v.x); t.y = f2tf32(v.y);
        t.z = f2tf32(v.z); t.w = f2tf32(v.w);
        *(uint4*)(smem + SA_OFF + sw_off(p, j16)) = t;
    }

    // W_k -> sB as W^T[n][i]
    {
        const float4* Wg = (const float4*)(kernel + k * CCH * CCH);
        #pragma unroll
        for (int s = 0; s < 8; s++) {
            int idx = tid + 128 * s;
            int i   = idx & 63;
            int o4  = idx >> 6;
            float4 v = Wg[i * 16 + o4];
            #pragma unroll
            for (int j = 0; j < 4; j++) {
                int n = o4 * 4 + j;
                float f = (j == 0) ? v.x : (j == 1) ? v.y : (j == 2) ? v.z : v.w;
                *(uint32_t*)(smem + SB_OFF + n * 256
                             + (((i >> 2) ^ (n & 7)) << 4) + (i & 3) * 4) = f2tf32(f);
            }
        }
    }
    __syncthreads();

    // GEMM: warp w -> rows [32w,32w+32) x 64 cols
    float acc[2][8][4];
    #pragma unroll
    for (int mt = 0; mt < 2; mt++)
        #pragma unroll
        for (int nt = 0; nt < 8; nt++)
            #pragma unroll
            for (int c = 0; c < 4; c++) acc[mt][nt][c] = 0.f;

    const int arow = 32 * w + (((l >> 3) & 1) << 3) + (l & 7);
    const int ahi  = l >> 4;
    const int asw  = arow & 7;
    const int brow = ((l >> 4) << 3) + (l & 7);
    const int bhi  = (l >> 3) & 1;
    const int bsw  = brow & 7;
    const uint32_t aBase = sb + SA_OFF + arow * 256;
    const uint32_t bBase = sb + SB_OFF + brow * 256;

    #pragma unroll
    for (int kk = 0; kk < 8; kk++) {
        uint32_t a[2][4];
        #pragma unroll
        for (int mt = 0; mt < 2; mt++) {
            uint32_t addr = aBase + mt * 4096 + ((((kk << 1) | ahi) ^ asw) << 4);
            LDSM_X4(a[mt][0], a[mt][1], a[mt][2], a[mt][3], addr);
        }
        uint32_t b[8][2];
        #pragma unroll
        for (int g = 0; g < 4; g++) {
            uint32_t r0, r1, r2, r3;
            uint32_t addr = bBase + g * 4096 + ((((kk << 1) | bhi) ^ bsw) << 4);
            LDSM_X4(r0, r1, r2, r3, addr);
            b[2 * g][0] = r0; b[2 * g][1] = r1;
            b[2 * g + 1][0] = r2; b[2 * g + 1][1] = r3;
        }
        #pragma unroll
        for (int mt = 0; mt < 2; mt++)
            #pragma unroll
            for (int nt = 0; nt < 8; nt++)
                MMA_TF32(acc[mt][nt], a[mt][0], a[mt][1], a[mt][2], a[mt][3],
                         b[nt][0], b[nt][1]);
    }

    // epilogue: butterfly shfl to 4 consecutive cols/lane, fp16 store to
    // sorted staging row (plain STG, no atomics)
    const int odd = l & 1;
    #pragma unroll
    for (int mt = 0; mt < 2; mt++) {
        int row = 32 * w + 16 * mt + (l >> 2) + (odd ? 8 : 0);
        int dst = sPerm[row];
        int cb  = 2 * (l & 3) - (odd ? 2 : 0);
        #pragma unroll
        for (int nt = 0; nt < 8; nt++) {
            float s0 = odd ? acc[mt][nt][0] : acc[mt][nt][2];
            float s1 = odd ? acc[mt][nt][1] : acc[mt][nt][3];
            float r0 = __shfl_xor_sync(0xffffffffu, s0, 1);
            float r1 = __shfl_xor_sync(0xffffffffu, s1, 1);
            float v0 = odd ? r0 : acc[mt][nt][0];
            float v1 = odd ? r1 : acc[mt][nt][1];
            float v2 = odd ? acc[mt][nt][2] : r0;
            float v3 = odd ? acc[mt][nt][3] : r1;
            if (dst >= 0) {
                __half2 h0 = __floats2half2_rn(v0, v1);
                __half2 h1 = __floats2half2_rn(v2, v3);
                uint2 u;
                u.x = *(uint32_t*)&h0;
                u.y = *(uint32_t*)&h1;
                *(uint2*)((char*)g_stage + (size_t)dst * 128 + (8 * nt + cb) * 2) = u;
            }
        }
    }
}

// ---------------- pass B: segment reduce + bias, single plain store ----------------

__global__ void __launch_bounds__(256) pass_b_kernel(
    const float* __restrict__ bias, float* __restrict__ out)
{
    int wid = threadIdx.x >> 5;
    int l   = threadIdx.x & 31;
    int o   = blockIdx.x * 8 + wid;          // 12500 blocks x 8 warps = 100000 rows
    if (o >= NPTS) return;

    int s0 = g_start[o];
    int s1 = g_start[o + 1];

    float2 acc = make_float2(0.f, 0.f);
    const unsigned int* p = g_stage + (size_t)s0 * 32 + l;
    int cnt = s1 - s0;
    #pragma unroll 4
    for (int t = 0; t < cnt; t++) {
        unsigned int u = p[t * 32];
        __half2 h = *(__half2*)&u;
        float2 f = __half22float2(h);
        acc.x += f.x;
        acc.y += f.y;
    }
    float2 b = *(const float2*)(bias + l * 2);
    acc.x += b.x;
    acc.y += b.y;
    *(float2*)(out + o * CCH + l * 2) = acc;
}

extern "C" void kernel_launch(void* const* d_in, const int* in_sizes, int n_in,
                              void* d_out, int out_size)
{
    const float* input  = (const float*)d_in[0];
    const float* kern   = (const float*)d_in[1];
    const float* bias   = (const float*)d_in[2];
    const int*   in_map = (const int*)  d_in[3];
    const int*   out_map= (const int*)  d_in[4];
    float* out = (float*)d_out;

    cudaFuncSetAttribute(pass_a_kernel,
                         cudaFuncAttributeMaxDynamicSharedMemorySize, SMEM_BYTES);

    // prepass: counting sort of pairs by output row
    zero_cnt_kernel<<<(NSCAN + 255) / 256, 256>>>();
    hist_kernel<<<(NPTOT + 255) / 256, 256>>>(out_map);
    scan_a_kernel<<<196, 512>>>();
    scan_b_kernel<<<1, 256>>>();
    scan_c_kernel<<<196, 512>>>();
    scatter_perm_kernel<<<(NPTOT + 255) / 256, 256>>>(out_map);

    // pass A: per-offset GEMM, results to sorted fp16 staging
    dim3 grid(NTILES, KVOL);
    pass_a_kernel<<<grid, 128, SMEM_BYTES>>>(input, kern, in_map);

    // pass B: contiguous segment reduction + bias
    pass_b_kernel<<<(NPTS + 7) / 8, 256>>>(bias, out);
}

// round 7
// speedup vs baseline: 1.1845x; 1.1845x over previous
#include <cuda_runtime.h>
#include <cstdint>

#define NPTS  100000
#define KVOL  27
#define PAIRS 60000
#define CCH   64
#define TP    128
#define NTILES ((PAIRS + TP - 1) / TP)

// smem: A 128x64 tf32 (swizzled rows of 256B) | B 64x64 tf32 (W^T, swizzled) | maps
#define SA_OFF 0
#define SB_OFF 32768
#define MAPS_OFF 49152
#define SMEM_BYTES 50176

// pre-transposed tf32 weights: [k][n][i] (n = out channel, i = K), 442KB, L2-resident
__device__ uint32_t g_wt[KVOL * CCH * CCH];

#define RED_V4(ptr, x, y, z, w) \
    asm volatile("red.global.add.v4.f32 [%0], {%1,%2,%3,%4};" \
                 :: "l"(ptr), "f"(x), "f"(y), "f"(z), "f"(w) : "memory")

__device__ __forceinline__ uint32_t smem_u32(const void* p) {
    uint32_t a;
    asm("{ .reg .u64 t; cvta.to.shared.u64 t, %1; cvt.u32.u64 %0, t; }"
        : "=r"(a) : "l"(p));
    return a;
}

__device__ __forceinline__ uint32_t f2tf32(float f) {
    uint32_t r;
    asm("cvt.rna.tf32.f32 %0, %1;" : "=r"(r) : "f"(f));
    return r;
}

#define LDSM_X4(r0, r1, r2, r3, addr) \
    asm volatile("ldmatrix.sync.aligned.m8n8.x4.shared.b16 {%0,%1,%2,%3}, [%4];" \
                 : "=r"(r0), "=r"(r1), "=r"(r2), "=r"(r3) : "r"(addr))

#define MMA_TF32(c, a0, a1, a2, a3, b0, b1) \
    asm volatile("mma.sync.aligned.m16n8k8.row.col.f32.tf32.tf32.f32 " \
                 "{%0,%1,%2,%3}, {%4,%5,%6,%7}, {%8,%9}, {%0,%1,%2,%3};" \
                 : "+f"(c[0]), "+f"(c[1]), "+f"(c[2]), "+f"(c[3]) \
                 : "r"(a0), "r"(a1), "r"(a2), "r"(a3), "r"(b0), "r"(b1))

__global__ void __launch_bounds__(256) init_bias_kernel(
    const float* __restrict__ bias, float* __restrict__ out)
{
    int idx = blockIdx.x * 256 + threadIdx.x;
    if (idx < NPTS * CCH) out[idx] = bias[idx & (CCH - 1)];
}

// one-time W transpose + tf32 convert: g_wt[k][n][i] = tf32(W[k][i][n])
__global__ void __launch_bounds__(256) prep_w_kernel(const float* __restrict__ kernel)
{
    __shared__ float s[64 * 65];          // padded: row i at s[i*65]
    const int k   = blockIdx.x;
    const int tid = threadIdx.x;
    const float* Wk = kernel + k * CCH * CCH;
    #pragma unroll
    for (int t = 0; t < 16; t++) {
        int e = tid + 256 * t;            // e = i*64 + n, coalesced read
        s[(e >> 6) * 65 + (e & 63)] = Wk[e];
    }
    __syncthreads();
    uint32_t* dst = g_wt + k * CCH * CCH;
    #pragma unroll
    for (int t = 0; t < 16; t++) {
        int j = tid + 256 * t;            // j = n*64 + i, coalesced write
        dst[j] = f2tf32(s[(j & 63) * 65 + (j >> 6)]);
    }
}

// swizzled byte offset inside a 256B row: chunk' = k16 ^ (row & 7)
__device__ __forceinline__ uint32_t sw_off(int row, int k16) {
    return (uint32_t)(row * 256 + ((k16 ^ (row & 7)) << 4));
}

__global__ void __launch_bounds__(128, 4) sparse_conv_kernel(
    const float* __restrict__ input,
    const int*   __restrict__ in_map,
    const int*   __restrict__ out_map,
    float*       __restrict__ out)
{
    extern __shared__ __align__(1024) char smem[];
    const uint32_t sb = smem_u32(smem);
    int* sIn  = (int*)(smem + MAPS_OFF);
    int* sOut = sIn + TP;

    const int k    = blockIdx.y;
    const int base = blockIdx.x * TP;
    const int tid  = threadIdx.x;
    const int w    = tid >> 5;
    const int l    = tid & 31;
    const int nrem = min(TP, PAIRS - base);

    // pair maps (coalesced)
    if (tid < nrem) {
        sIn[tid]  = in_map [k * PAIRS + base + tid];
        sOut[tid] = out_map[k * PAIRS + base + tid];
    } else {
        sIn[tid] = -1;
        sOut[tid] = -1;
    }
    __syncthreads();

    // ---- gather X -> sA (tf32, swizzled). 16 lanes per row: coalesced 256B
    // gmem reads, conflict-free STS.128 ----
    #pragma unroll
    for (int s = 0; s < 16; s++) {
        int m   = tid + 128 * s;
        int p   = m >> 4;
        int j16 = m & 15;
        int row = sIn[p];
        float4 v = make_float4(0.f, 0.f, 0.f, 0.f);
        if (row >= 0) v = ((const float4*)input)[row * (CCH / 4) + j16];
        uint4 t;
        t.x = f2tf32(v.x); t.y = f2tf32(v.y);
        t.z = f2tf32(v.z); t.w = f2tf32(v.w);
        *(uint4*)(smem + SA_OFF + sw_off(p, j16)) = t;
    }

    // ---- W^T (pre-transposed tf32) -> sB: consecutive float4s, coalesced LDG,
    // conflict-free swizzled STS (same pattern as the A path) ----
    {
        const uint4* Wt = (const uint4*)(g_wt + k * CCH * CCH);
        #pragma unroll
        for (int s = 0; s < 8; s++) {
            int m   = tid + 128 * s;      // 1024 float4s: n = m>>4, chunk = m&15
            int n   = m >> 4;
            int j16 = m & 15;
            *(uint4*)(smem + SB_OFF + sw_off(n, j16)) = Wt[m];
        }
    }
    __syncthreads();

    // ---- GEMM via mma.sync tf32: warp w computes rows [32w,32w+32) x 64 cols ----
    float acc[2][8][4];
    #pragma unroll
    for (int mt = 0; mt < 2; mt++)
        #pragma unroll
        for (int nt = 0; nt < 8; nt++)
            #pragma unroll
            for (int c = 0; c < 4; c++) acc[mt][nt][c] = 0.f;

    const int arow = 32 * w + (((l >> 3) & 1) << 3) + (l & 7);  // + 16*mt
    const int ahi  = l >> 4;
    const int asw  = arow & 7;
    const int brow = ((l >> 4) << 3) + (l & 7);                 // + n0
    const int bhi  = (l >> 3) & 1;
    const int bsw  = brow & 7;
    const uint32_t aBase = sb + SA_OFF + arow * 256;
    const uint32_t bBase = sb + SB_OFF + brow * 256;

    #pragma unroll
    for (int kk = 0; kk < 8; kk++) {
        uint32_t a[2][4];
        #pragma unroll
        for (int mt = 0; mt < 2; mt++) {
            uint32_t addr = aBase + mt * 4096 + ((((kk << 1) | ahi) ^ asw) << 4);
            LDSM_X4(a[mt][0], a[mt][1], a[mt][2], a[mt][3], addr);
        }
        uint32_t b[8][2];
        #pragma unroll
        for (int g = 0; g < 4; g++) {
            uint32_t r0, r1, r2, r3;
            uint32_t addr = bBase + g * 4096 + ((((kk << 1) | bhi) ^ bsw) << 4);
            LDSM_X4(r0, r1, r2, r3, addr);
            b[2 * g][0] = r0; b[2 * g][1] = r1;
            b[2 * g + 1][0] = r2; b[2 * g + 1][1] = r3;
        }
        #pragma unroll
        for (int mt = 0; mt < 2; mt++)
            #pragma unroll
            for (int nt = 0; nt < 8; nt++)
                MMA_TF32(acc[mt][nt], a[mt][0], a[mt][1], a[mt][2], a[mt][3],
                         b[nt][0], b[nt][1]);
    }

    // ---- scatter-add: butterfly shfl (l^1) -> one guarded red.v4 per (mt,nt) ----
    const int odd = l & 1;
    #pragma unroll
    for (int mt = 0; mt < 2; mt++) {
        int row = 32 * w + 16 * mt + (l >> 2) + (odd ? 8 : 0);
        int o   = sOut[row];
        int cb  = 2 * (l & 3) - (odd ? 2 : 0);
        #pragma unroll
        for (int nt = 0; nt < 8; nt++) {
            float s0 = odd ? acc[mt][nt][0] : acc[mt][nt][2];
            float s1 = odd ? acc[mt][nt][1] : acc[mt][nt][3];
            float r0 = __shfl_xor_sync(0xffffffffu, s0, 1);
            float r1 = __shfl_xor_sync(0xffffffffu, s1, 1);
            float v0 = odd ? r0 : acc[mt][nt][0];
            float v1 = odd ? r1 : acc[mt][nt][1];
            float v2 = odd ? acc[mt][nt][2] : r0;
            float v3 = odd ? acc[mt][nt][3] : r1;
            if (o >= 0)
                RED_V4(out + o * CCH + 8 * nt + cb, v0, v1, v2, v3);
        }
    }
}

extern "C" void kernel_launch(void* const* d_in, const int* in_sizes, int n_in,
                              void* d_out, int out_size)
{
    const float* input  = (const float*)d_in[0];
    const float* kern   = (const float*)d_in[1];
    const float* bias   = (const float*)d_in[2];
    const int*   in_map = (const int*)  d_in[3];
    const int*   out_map= (const int*)  d_in[4];
    float* out = (float*)d_out;

    cudaFuncSetAttribute(sparse_conv_kernel,
                         cudaFuncAttributeMaxDynamicSharedMemorySize, SMEM_BYTES);

    prep_w_kernel<<<KVOL, 256>>>(kern);
    init_bias_kernel<<<(NPTS * CCH + 255) / 256, 256>>>(bias, out);

    dim3 grid(NTILES, KVOL);
    sparse_conv_kernel<<<grid, 128, SMEM_BYTES>>>(input, in_map, out_map, out);
}

// round 8
// speedup vs baseline: 1.4342x; 1.2108x over previous
#include <cuda_runtime.h>
#include <cstdint>

#define NPTS  100000
#define KVOL  27
#define PAIRS 60000
#define CCH   64
#define TP    128
#define NTILES ((PAIRS + TP - 1) / TP)

// smem: A 128x64 tf32 (swizzled rows of 256B) | B 64x64 tf32 (W^T, swizzled) | maps
#define SA_OFF 0
#define SB_OFF 32768
#define MAPS_OFF 49152
#define SMEM_BYTES 50176

#define RED_V4(ptr, x, y, z, w) \
    asm volatile("red.global.add.v4.f32 [%0], {%1,%2,%3,%4};" \
                 :: "l"(ptr), "f"(x), "f"(y), "f"(z), "f"(w) : "memory")

__device__ __forceinline__ uint32_t smem_u32(const void* p) {
    uint32_t a;
    asm("{ .reg .u64 t; cvta.to.shared.u64 t, %1; cvt.u32.u64 %0, t; }"
        : "=r"(a) : "l"(p));
    return a;
}

__device__ __forceinline__ uint32_t f2tf32(float f) {
    uint32_t r;
    asm("cvt.rna.tf32.f32 %0, %1;" : "=r"(r) : "f"(f));
    return r;
}

#define LDSM_X4(r0, r1, r2, r3, addr) \
    asm volatile("ldmatrix.sync.aligned.m8n8.x4.shared.b16 {%0,%1,%2,%3}, [%4];" \
                 : "=r"(r0), "=r"(r1), "=r"(r2), "=r"(r3) : "r"(addr))

#define MMA_TF32(c, a0, a1, a2, a3, b0, b1) \
    asm volatile("mma.sync.aligned.m16n8k8.row.col.f32.tf32.tf32.f32 " \
                 "{%0,%1,%2,%3}, {%4,%5,%6,%7}, {%8,%9}, {%0,%1,%2,%3};" \
                 : "+f"(c[0]), "+f"(c[1]), "+f"(c[2]), "+f"(c[3]) \
                 : "r"(a0), "r"(a1), "r"(a2), "r"(a3), "r"(b0), "r"(b1))

__global__ void __launch_bounds__(256) init_bias_kernel(
    const float* __restrict__ bias, float* __restrict__ out)
{
    int idx = blockIdx.x * 256 + threadIdx.x;
    if (idx < NPTS * CCH) out[idx] = bias[idx & (CCH - 1)];
}

// swizzled byte offset inside a 256B row: chunk' = k16 ^ (row & 7)
__device__ __forceinline__ uint32_t sw_off(int row, int k16) {
    return (uint32_t)(row * 256 + ((k16 ^ (row & 7)) << 4));
}

__global__ void __launch_bounds__(256, 3) sparse_conv_kernel(
    const float* __restrict__ input,
    const float* __restrict__ kernel,
    const int*   __restrict__ in_map,
    const int*   __restrict__ out_map,
    float*       __restrict__ out)
{
    extern __shared__ __align__(1024) char smem[];
    const uint32_t sb = smem_u32(smem);
    int* sIn  = (int*)(smem + MAPS_OFF);
    int* sOut = sIn + TP;

    const int k    = blockIdx.y;
    const int base = blockIdx.x * TP;
    const int tid  = threadIdx.x;
    const int w    = tid >> 5;
    const int l    = tid & 31;
    const int band = w >> 1;          // 0..3: 32-row band
    const int half = w & 1;           // 0..1: 32-col half
    const int nrem = min(TP, PAIRS - base);

    // pair maps (coalesced)
    if (tid < TP) {
        if (tid < nrem) {
            sIn[tid]  = in_map [k * PAIRS + base + tid];
            sOut[tid] = out_map[k * PAIRS + base + tid];
        } else {
            sIn[tid] = -1;
            sOut[tid] = -1;
        }
    }
    __syncthreads();

    // ---- gather X -> sA (tf32, swizzled). 16 lanes per row: coalesced 256B
    // gmem reads, conflict-free STS.128 ----
    #pragma unroll
    for (int s = 0; s < 8; s++) {
        int m   = tid + 256 * s;
        int p   = m >> 4;
        int j16 = m & 15;
        int row = sIn[p];
        float4 v = make_float4(0.f, 0.f, 0.f, 0.f);
        if (row >= 0) v = ((const float4*)input)[row * (CCH / 4) + j16];
        uint4 t;
        t.x = f2tf32(v.x); t.y = f2tf32(v.y);
        t.z = f2tf32(v.z); t.w = f2tf32(v.w);
        *(uint4*)(smem + SA_OFF + sw_off(p, j16)) = t;
    }

    // ---- W_k -> sB as W^T[n][i] (row n = out channel, 64 tf32 over K) ----
    {
        const float4* Wg = (const float4*)(kernel + k * CCH * CCH);
        #pragma unroll
        for (int s = 0; s < 4; s++) {
            int idx = tid + 256 * s;
            int i   = idx & 63;          // K index
            int o4  = idx >> 6;          // group of 4 output channels
            float4 v = Wg[i * 16 + o4];
            #pragma unroll
            for (int j = 0; j < 4; j++) {
                int n = o4 * 4 + j;
                float f = (j == 0) ? v.x : (j == 1) ? v.y : (j == 2) ? v.z : v.w;
                *(uint32_t*)(smem + SB_OFF + n * 256
                             + (((i >> 2) ^ (n & 7)) << 4) + (i & 3) * 4) = f2tf32(f);
            }
        }
    }
    __syncthreads();

    // ---- GEMM via mma.sync tf32: warp (band,half) computes
    // rows [32*band, 32*band+32) x cols [32*half, 32*half+32) ----
    float acc[2][4][4];
    #pragma unroll
    for (int mt = 0; mt < 2; mt++)
        #pragma unroll
        for (int nt = 0; nt < 4; nt++)
            #pragma unroll
            for (int c = 0; c < 4; c++) acc[mt][nt][c] = 0.f;

    const int arow = 32 * band + (((l >> 3) & 1) << 3) + (l & 7);  // + 16*mt
    const int ahi  = l >> 4;
    const int asw  = arow & 7;
    const int brow = ((l >> 4) << 3) + (l & 7);                    // + n0
    const int bhi  = (l >> 3) & 1;
    const int bsw  = brow & 7;
    const uint32_t aBase = sb + SA_OFF + arow * 256;
    const uint32_t bBase = sb + SB_OFF + brow * 256;

    #pragma unroll
    for (int kk = 0; kk < 8; kk++) {
        uint32_t a[2][4];
        #pragma unroll
        for (int mt = 0; mt < 2; mt++) {
            uint32_t addr = aBase + mt * 4096 + ((((kk << 1) | ahi) ^ asw) << 4);
            LDSM_X4(a[mt][0], a[mt][1], a[mt][2], a[mt][3], addr);
        }
        uint32_t b[4][2];
        #pragma unroll
        for (int gl = 0; gl < 2; gl++) {          // g = 2*half + gl, n0 = 16g
            int g = 2 * half + gl;
            uint32_t r0, r1, r2, r3;
            uint32_t addr = bBase + g * 4096 + ((((kk << 1) | bhi) ^ bsw) << 4);
            LDSM_X4(r0, r1, r2, r3, addr);
            b[2 * gl][0] = r0; b[2 * gl][1] = r1;
            b[2 * gl + 1][0] = r2; b[2 * gl + 1][1] = r3;
        }
        #pragma unroll
        for (int mt = 0; mt < 2; mt++)
            #pragma unroll
            for (int nt = 0; nt < 4; nt++)
                MMA_TF32(acc[mt][nt], a[mt][0], a[mt][1], a[mt][2], a[mt][3],
                         b[nt][0], b[nt][1]);
    }

    // ---- scatter-add: butterfly shfl (l^1) -> one guarded red.v4 per (mt,nt) ----
    const int odd = l & 1;
    #pragma unroll
    for (int mt = 0; mt < 2; mt++) {
        int row = 32 * band + 16 * mt + (l >> 2) + (odd ? 8 : 0);
        int o   = sOut[row];
        int cb  = 2 * (l & 3) - (odd ? 2 : 0);
        #pragma unroll
        for (int nt = 0; nt < 4; nt++) {
            int col = 8 * (4 * half + nt) + cb;
            float s0 = odd ? acc[mt][nt][0] : acc[mt][nt][2];
            float s1 = odd ? acc[mt][nt][1] : acc[mt][nt][3];
            float r0 = __shfl_xor_sync(0xffffffffu, s0, 1);
            float r1 = __shfl_xor_sync(0xffffffffu, s1, 1);
            float v0 = odd ? r0 : acc[mt][nt][0];
            float v1 = odd ? r1 : acc[mt][nt][1];
            float v2 = odd ? acc[mt][nt][2] : r0;
            float v3 = odd ? acc[mt][nt][3] : r1;
            if (o >= 0)
                RED_V4(out + o * CCH + col, v0, v1, v2, v3);
        }
    }
}

extern "C" void kernel_launch(void* const* d_in, const int* in_sizes, int n_in,
                              void* d_out, int out_size)
{
    const float* input  = (const float*)d_in[0];
    const float* kern   = (const float*)d_in[1];
    const float* bias   = (const float*)d_in[2];
    const int*   in_map = (const int*)  d_in[3];
    const int*   out_map= (const int*)  d_in[4];
    float* out = (float*)d_out;

    cudaFuncSetAttribute(sparse_conv_kernel,
                         cudaFuncAttributeMaxDynamicSharedMemorySize, SMEM_BYTES);

    init_bias_kernel<<<(NPTS * CCH + 255) / 256, 256>>>(bias, out);

    dim3 grid(NTILES, KVOL);
    sparse_conv_kernel<<<grid, 256, SMEM_BYTES>>>(input, kern, in_map, out_map, out);
}